// round 15
// baseline (speedup 1.0000x reference)
#include <cuda_runtime.h>
#include <math.h>

#define KNN 20
#define NPTS 8192
typedef unsigned long long ull;
typedef unsigned short ushort_t;

// ---------------- scratch ----------------
__device__ __align__(256) float g_feat[NPTS * 192];
__device__ __align__(256) float g_u[NPTS * 64];
__device__ __align__(256) float g_v[NPTS * 64];
__device__ __align__(256) float g_sq[NPTS];
__device__ __align__(256) int   g_idx[NPTS * KNN];
__device__ __align__(256) float g_h1[NPTS * 1024];
__device__ __align__(256) float g_h2[NPTS * 256];
__device__ __align__(256) float g_h3[NPTS * 128];

__device__ __forceinline__ void fma2(ull& d, ull a, ull b) {
    asm("fma.rn.f32x2 %0, %1, %2, %0;" : "+l"(d) : "l"(a), "l"(b));
}
__device__ __forceinline__ float sum2(ull u) {
    return __uint_as_float((unsigned)u) + __uint_as_float((unsigned)(u >> 32));
}

// ---------------- squared norms ----------------
__global__ void sqn_kernel(const float* __restrict__ X, int ldx, int C,
                           float* __restrict__ sq, int N)
{
    int i = blockIdx.x * blockDim.x + threadIdx.x;
    if (i < N) {
        float s = 0.f;
        for (int c = 0; c < C; c++) { float v = X[i * ldx + c]; s = fmaf(v, v, s); }
        sq[i] = s;
    }
}

// ---------------- kNN C=3: pre-gated append-buffer selection (R14, committed) ----------------
template<int TJ, int WARPS>
__global__ void __launch_bounds__(256)
knn3_kernel(const float* __restrict__ X,
            const float* __restrict__ sqn,
            int* __restrict__ idx, int N)
{
    extern __shared__ float4 sh4[];
    float4* sP = sh4;                          // [TJ]
    float*  cd = (float*)(sP + TJ);            // WARPS*32*21
    int*    ci = (int*)(cd + WARPS * 32 * 21);

    const int warpId = threadIdx.x >> 5;
    const int lane   = threadIdx.x & 31;
    const int row    = blockIdx.x * WARPS + warpId;

    const float xa = -2.f * X[row * 3 + 0];
    const float xb = -2.f * X[row * 3 + 1];
    const float xc = -2.f * X[row * 3 + 2];

    float* myd = cd + (warpId * 32 + lane) * 21;
    int*   myi = ci + (warpId * 32 + lane) * 21;
    #pragma unroll
    for (int t = 0; t < KNN; t++) { myd[t] = INFINITY; myi[t] = 0x7fffffff; }
    int   count = 0;
    float worst = INFINITY;
    int   worstpos = 0;
    float lane_min = INFINITY;
    float wgate;

    {
        const float* xr = X + threadIdx.x * 3;
        sP[threadIdx.x] = make_float4(xr[0], xr[1], xr[2], sqn[threadIdx.x]);
    }
    __syncthreads();
    {
        float mn = INFINITY;
        #pragma unroll
        for (int q = 0; q < TJ / 32; q++) {
            float4 p = sP[q * 32 + lane];
            mn = fminf(mn, fmaf(xa, p.x, fmaf(xb, p.y, fmaf(xc, p.z, p.w))));
        }
        lane_min = mn;
        float m = mn;
        #pragma unroll
        for (int off = 16; off; off >>= 1)
            m = fmaxf(m, __shfl_xor_sync(~0u, m, off));
        wgate = m;
    }

    for (int base = 0; base < N; base += TJ) {
        __syncthreads();
        {
            const float* xr = X + (base + threadIdx.x) * 3;
            sP[threadIdx.x] = make_float4(xr[0], xr[1], xr[2], sqn[base + threadIdx.x]);
        }
        __syncthreads();

        float dv[TJ / 32];
        float mn = INFINITY;
        #pragma unroll
        for (int q = 0; q < TJ / 32; q++) {
            float4 p = sP[q * 32 + lane];
            float d = fmaf(xa, p.x, fmaf(xb, p.y, fmaf(xc, p.z, p.w)));
            dv[q] = d;
            mn = fminf(mn, d);
        }
        lane_min = fminf(lane_min, mn);
        if (mn < fminf(worst, wgate)) {
            #pragma unroll
            for (int q = 0; q < TJ / 32; q++) {
                float d = dv[q];
                int   j = base + q * 32 + lane;
                if (d < fminf(worst, wgate) && j != row) {
                    if (count < KNN) {
                        myd[count] = d;
                        myi[count] = j;
                        count++;
                        if (count == KNN) {
                            worst = -INFINITY;
                            #pragma unroll
                            for (int t = 0; t < KNN; t++) {
                                float v = myd[t];
                                if (v > worst) { worst = v; worstpos = t; }
                            }
                        }
                    } else {
                        myd[worstpos] = d;
                        myi[worstpos] = j;
                        worst = -INFINITY;
                        #pragma unroll
                        for (int t = 0; t < KNN; t++) {
                            float v = myd[t];
                            if (v > worst) { worst = v; worstpos = t; }
                        }
                    }
                }
            }
        }
        {
            float m = lane_min;
            #pragma unroll
            for (int off = 16; off; off >>= 1)
                m = fmaxf(m, __shfl_xor_sync(~0u, m, off));
            wgate = m;
        }
    }

    __syncwarp();
    for (int r = 0; r < KNN; r++) {
        float bv = INFINITY; int bj = 0x7fffffff, bp = 0, bl = lane;
        #pragma unroll
        for (int t = 0; t < KNN; t++) {
            float v = myd[t]; int jv = myi[t];
            if (v < bv || (v == bv && jv < bj)) { bv = v; bj = jv; bp = t; }
        }
        #pragma unroll
        for (int off = 16; off; off >>= 1) {
            float ov = __shfl_xor_sync(~0u, bv, off);
            int   oj = __shfl_xor_sync(~0u, bj, off);
            int   ol = __shfl_xor_sync(~0u, bl, off);
            int   op = __shfl_xor_sync(~0u, bp, off);
            if (ov < bv || (ov == bv && oj < bj)) { bv = ov; bj = oj; bl = ol; bp = op; }
        }
        if (lane == bl) myd[bp] = INFINITY;
        if (lane == 0)  idx[row * KNN + r] = bj;
        __syncwarp();
    }
}

// ---------------- kNN C=64: 128-cand tiles for 2 CTAs/SM ----------------
// 256 thr (8 warps), 64 rows/block, 128-candidate tiles, 33 k-pairs (last = norm).
// Warp w: rows (w>>1)*16..+15, cand half (w&1)*64; lane = 2 cands. acc 16x2.
// smem ~115.5 KB -> 2 blocks/SM (4 warps/SMSP hides LDS latency).
#define SDK 132   // sDist row stride (2 segments of 66)
__global__ void __launch_bounds__(256, 2)
knn64_kernel(const float* __restrict__ X, int ldx, const float* __restrict__ sqn,
             int* __restrict__ idx, int N)
{
    extern __shared__ float sh[];
    float2*   Qs2   = (float2*)sh;                   // [33][64]
    float2*   Cs2   = Qs2 + 33 * 64;                 // [33][128] swizzled
    float*    sDist = (float*)(Cs2 + 33 * 128);      // [64][132]
    float*    Ld    = sDist + 64 * SDK;              // [256][20]
    ushort_t* Lj    = (ushort_t*)(Ld + 256 * 20);    // [256][20]
    float*    sThr  = (float*)(Lj + 256 * 20 + 16);  // [64]

    const int tid  = threadIdx.x;
    const int w    = tid >> 5, tx = tid & 31;
    const int rowg = w >> 1, colh = w & 1;
    const int rowBase = blockIdx.x * 64;

    if (tid < 64) sThr[tid] = INFINITY;

    // --- Q tile (64 rows x 32 k-pairs + norm pair) ---
    {
        int r = tid >> 2, part = tid & 3;
        const float* xr = X + (rowBase + r) * ldx + part * 16;
        #pragma unroll
        for (int i = 0; i < 4; i++) {
            float4 v = *(const float4*)(xr + i * 4);
            int kp = part * 8 + i * 2;
            Qs2[kp * 64 + r]       = make_float2(v.x, v.y);
            Qs2[(kp + 1) * 64 + r] = make_float2(v.z, v.w);
        }
        if (part == 0) Qs2[32 * 64 + r] = make_float2(-0.5f, -0.5f);
    }

    const int selR = tid >> 2, selS = tid & 3;
    const int grow = rowBase + selR;
    float*    myLd = Ld + tid * 20;
    ushort_t* myLj = Lj + tid * 20;
    #pragma unroll
    for (int t = 0; t < KNN; t++) myLd[t] = INFINITY;
    float wd = INFINITY;
    int   wpos = 0;

    for (int base = 0; base < N; base += 128) {
        __syncthreads();
        // --- coalesced 128-cand tile load, swizzled store ---
        {
            int q = tid & 15, c0 = tid >> 4;
            int sxr = (q & 7) * 2;
            #pragma unroll
            for (int i = 0; i < 8; i++) {
                int c = c0 + i * 16;
                float4 v = *(const float4*)(X + (base + c) * ldx + q * 4);
                int cs = c ^ sxr;
                Cs2[(2 * q)     * 128 + cs] = make_float2(v.x, v.y);
                Cs2[(2 * q + 1) * 128 + cs] = make_float2(v.z, v.w);
            }
            if (tid < 128)
                Cs2[32 * 128 + tid] = make_float2(sqn[base + tid], 0.f);
        }
        __syncthreads();

        // --- GEMM: 16 rows x 2 cands per thread over 33 k-pairs ---
        ull acc[16][2];
        #pragma unroll
        for (int m = 0; m < 16; m++) { acc[m][0] = 0ull; acc[m][1] = 0ull; }

        #pragma unroll 3
        for (int kp = 0; kp < 33; kp++) {
            int sxr = ((kp >> 1) & 7) * 2;
            ulonglong2 B = *(const ulonglong2*)(Cs2 + kp * 128 + ((colh * 64 + tx * 2) ^ sxr));
            const ulonglong2* pa = (const ulonglong2*)(Qs2 + kp * 64 + rowg * 16);
            #pragma unroll
            for (int i = 0; i < 8; i++) {
                ulonglong2 A = pa[i];
                fma2(acc[2*i][0],   A.x, B.x); fma2(acc[2*i][1],   A.x, B.y);
                fma2(acc[2*i+1][0], A.y, B.x); fma2(acc[2*i+1][1], A.y, B.y);
            }
        }

        // --- epilogue: dist = -2*sum2 -> sDist (segment layout) ---
        #pragma unroll
        for (int i = 0; i < 16; i++) {
            int row = rowg * 16 + i;
            float* dr = sDist + row * SDK + colh * 66 + tx * 2;
            *(float2*)dr = make_float2(-2.f * sum2(acc[i][0]), -2.f * sum2(acc[i][1]));
        }
        __syncthreads();

        // --- selection: gated prefilter over this thread's 32-col segment ---
        {
            const float* bp = sDist + selR * SDK + (selS >> 1) * 66 + (selS & 1) * 32;
            const float thrS = sThr[selR];
            float gate = fminf(wd, thrS);
            float mn = INFINITY;
            #pragma unroll
            for (int o = 0; o < 32; o += 2) {
                float2 v = *(const float2*)(bp + o);
                mn = fminf(mn, fminf(v.x, v.y));
            }
            if (mn < gate) {
                int jb = base + selS * 32;
                #pragma unroll 8
                for (int o = 0; o < 32; o++) {
                    float d = bp[o];
                    if (d < gate && (jb + o) != grow) {
                        myLd[wpos] = d;
                        myLj[wpos] = (ushort_t)(jb + o);
                        wd = -INFINITY;
                        #pragma unroll
                        for (int t = 0; t < KNN; t++) {
                            float v = myLd[t];
                            if (v > wd) { wd = v; wpos = t; }
                        }
                        gate = fminf(wd, thrS);
                    }
                }
                if (wd < sThr[selR]) sThr[selR] = wd;   // racy min: valid upper bound
            }
        }
    }

    __syncthreads();
    // --- tail merge: thread selS==0 picks 20-of-80 for its row ---
    if (selS == 0) {
        #pragma unroll 1
        for (int k = 0; k < KNN; k++) {
            float bd = INFINITY; int bj = 0x7fffffff;
            int bslot = 0;
            #pragma unroll 1
            for (int tt = 0; tt < 4; tt++) {
                int lb = (tid + tt) * 20;
                #pragma unroll 4
                for (int t = 0; t < KNN; t++) {
                    float d = Ld[lb + t];
                    int   j = (int)Lj[lb + t];
                    if (d < bd || (d == bd && j < bj)) { bd = d; bj = j; bslot = lb + t; }
                }
            }
            Ld[bslot] = INFINITY;
            idx[grow * KNN + k] = bj;
        }
    }
}

// ---------------- EdgeConv U/V ----------------
template<int C>
__global__ void uv_kernel(const float* __restrict__ X, int ldx,
                          const float* __restrict__ w,
                          float* __restrict__ U, float* __restrict__ V, int N)
{
    __shared__ float sw[2 * C * 64];
    __shared__ float sx[4][C > 0 ? C : 1];
    int tid = threadIdx.y * 64 + threadIdx.x;
    for (int t = tid; t < 2 * C * 64; t += 256) sw[t] = w[t];
    int i = blockIdx.x * 4 + threadIdx.y;
    for (int c = threadIdx.x; c < C; c += 64) sx[threadIdx.y][c] = X[i * ldx + c];
    __syncthreads();

    int f = threadIdx.x;
    float u = 0.f, v = 0.f;
    #pragma unroll
    for (int c = 0; c < C; c++) {
        float xc = sx[threadIdx.y][c];
        u = fmaf(xc, sw[c * 64 + f], u);
        v = fmaf(xc, sw[(C + c) * 64 + f], v);
    }
    U[i * 64 + f] = u - v;
    V[i * 64 + f] = v;
}

// ---------------- neighbor gather-max + relu ----------------
__global__ void edge_max_kernel(const float* __restrict__ U, const float* __restrict__ V,
                                const float* __restrict__ b, const int* __restrict__ idx,
                                float* __restrict__ out, int ldo, int colofs, int N)
{
    __shared__ int sidx[4][KNN];
    int i = blockIdx.x * 4 + threadIdx.y;
    if (threadIdx.x < KNN) sidx[threadIdx.y][threadIdx.x] = idx[i * KNN + threadIdx.x];
    __syncthreads();

    int f = threadIdx.x;
    float m = -INFINITY;
    #pragma unroll
    for (int t = 0; t < KNN; t++) {
        int j = sidx[threadIdx.y][t];
        m = fmaxf(m, V[j * 64 + f]);
    }
    float val = U[i * 64 + f] + b[f] + m;
    out[i * ldo + colofs + f] = fmaxf(val, 0.f);
}

// ---------------- f32x2 SGEMM 64x256, fused bias+relu ----------------
__global__ void __launch_bounds__(256, 1)
gemm_f2_64x256(const float* __restrict__ A, int lda,
               const float* __restrict__ B, int ldb,
               const float* __restrict__ bias,
               float* __restrict__ C, int ldc, int K)
{
    __shared__ float2 As2[16][64];
    __shared__ float2 Bs2[16][256];

    const int tid = threadIdx.x;
    const int ty  = tid >> 5, tx = tid & 31;
    const int rowBase = blockIdx.y * 64;
    const int colBase = blockIdx.x * 256;

    ull acc[8][8];
    #pragma unroll
    for (int m = 0; m < 8; m++)
        #pragma unroll
        for (int n = 0; n < 8; n++) acc[m][n] = 0ull;

    const int ar = tid >> 2, ac = (tid & 3) * 8;
    const int bkp = tid >> 4, bc0 = (tid & 15) * 4;

    for (int k0 = 0; k0 < K; k0 += 32) {
        float4 v0 = *(const float4*)&A[(rowBase + ar) * lda + k0 + ac];
        float4 v1 = *(const float4*)&A[(rowBase + ar) * lda + k0 + ac + 4];
        float4 blo[4], bhi[4];
        #pragma unroll
        for (int rep = 0; rep < 4; rep++) {
            int col = colBase + rep * 64 + bc0;
            blo[rep] = *(const float4*)&B[(k0 + 2 * bkp) * ldb + col];
            bhi[rep] = *(const float4*)&B[(k0 + 2 * bkp + 1) * ldb + col];
        }
        __syncthreads();
        As2[(ac >> 1) + 0][ar] = make_float2(v0.x, v0.y);
        As2[(ac >> 1) + 1][ar] = make_float2(v0.z, v0.w);
        As2[(ac >> 1) + 2][ar] = make_float2(v1.x, v1.y);
        As2[(ac >> 1) + 3][ar] = make_float2(v1.z, v1.w);
        #pragma unroll
        for (int rep = 0; rep < 4; rep++) {
            int c = rep * 64 + bc0;
            Bs2[bkp][c + 0] = make_float2(blo[rep].x, bhi[rep].x);
            Bs2[bkp][c + 1] = make_float2(blo[rep].y, bhi[rep].y);
            Bs2[bkp][c + 2] = make_float2(blo[rep].z, bhi[rep].z);
            Bs2[bkp][c + 3] = make_float2(blo[rep].w, bhi[rep].w);
        }
        __syncthreads();

        #pragma unroll 4
        for (int kp = 0; kp < 16; kp++) {
            ull a[8], b[8];
            const ulonglong2* pa0 = (const ulonglong2*)(&As2[kp][ty * 4]);
            const ulonglong2* pa1 = (const ulonglong2*)(&As2[kp][32 + ty * 4]);
            ulonglong2 A0 = pa0[0], A1 = pa0[1], A2 = pa1[0], A3 = pa1[1];
            a[0] = A0.x; a[1] = A0.y; a[2] = A1.x; a[3] = A1.y;
            a[4] = A2.x; a[5] = A2.y; a[6] = A3.x; a[7] = A3.y;
            #pragma unroll
            for (int ch = 0; ch < 4; ch++) {
                ulonglong2 Bv = *(const ulonglong2*)(&Bs2[kp][ch * 64 + tx * 2]);
                b[2 * ch] = Bv.x; b[2 * ch + 1] = Bv.y;
            }
            #pragma unroll
            for (int m = 0; m < 8; m++)
                #pragma unroll
                for (int n = 0; n < 8; n++)
                    fma2(acc[m][n], a[m], b[n]);
        }
    }

    #pragma unroll
    for (int m = 0; m < 8; m++) {
        int row = rowBase + ((m < 4) ? (ty * 4 + m) : (32 + ty * 4 + (m - 4)));
        #pragma unroll
        for (int ch = 0; ch < 4; ch++) {
            int col = colBase + ch * 64 + tx * 2;
            float d0 = fmaxf(sum2(acc[m][2 * ch])     + bias[col],     0.f);
            float d1 = fmaxf(sum2(acc[m][2 * ch + 1]) + bias[col + 1], 0.f);
            *(float2*)&C[row * ldc + col] = make_float2(d0, d1);
        }
    }
}

// ---------------- small SGEMM (wm2) ----------------
__global__ void sgemm_bias_relu(const float* __restrict__ A, int lda,
                                const float* __restrict__ B, int ldb,
                                const float* __restrict__ bias,
                                float* __restrict__ Cm, int ldc,
                                int Kdim, int relu)
{
    __shared__ float As[16][68];
    __shared__ float Bs[16][64];
    const int tid = threadIdx.x;
    const int tx = tid & 15, ty = tid >> 4;
    const int rowBase = blockIdx.y * 64;
    const int colBase = blockIdx.x * 64;

    const int ar = tid >> 2, akq = (tid & 3) * 4;
    const int bk = tid >> 4, bc = (tid & 15) * 4;

    float acc[4][4] = {};
    for (int k0 = 0; k0 < Kdim; k0 += 16) {
        float4 av = *(const float4*)&A[(rowBase + ar) * lda + k0 + akq];
        float4 bv = *(const float4*)&B[(k0 + bk) * ldb + colBase + bc];
        __syncthreads();
        As[akq + 0][ar] = av.x; As[akq + 1][ar] = av.y;
        As[akq + 2][ar] = av.z; As[akq + 3][ar] = av.w;
        *(float4*)&Bs[bk][bc] = bv;
        __syncthreads();
        #pragma unroll
        for (int kk = 0; kk < 16; kk++) {
            float a[4], bb[4];
            #pragma unroll
            for (int m = 0; m < 4; m++) a[m] = As[kk][ty * 4 + m];
            #pragma unroll
            for (int n = 0; n < 4; n++) bb[n] = Bs[kk][tx * 4 + n];
            #pragma unroll
            for (int m = 0; m < 4; m++)
                #pragma unroll
                for (int n = 0; n < 4; n++)
                    acc[m][n] = fmaf(a[m], bb[n], acc[m][n]);
        }
    }
    #pragma unroll
    for (int m = 0; m < 4; m++) {
        int r = rowBase + ty * 4 + m;
        #pragma unroll
        for (int n = 0; n < 4; n++) {
            int c = colBase + tx * 4 + n;
            float v = acc[m][n] + bias[c];
            if (relu) v = fmaxf(v, 0.f);
            Cm[r * ldc + c] = v;
        }
    }
}

// ---------------- final 128->13 + log_softmax ----------------
__global__ void final_logsoftmax(const float* __restrict__ H,
                                 const float* __restrict__ W,
                                 const float* __restrict__ b,
                                 float* __restrict__ out, int N)
{
    __shared__ float sw[128 * 13];
    __shared__ float sb[13];
    int tid = threadIdx.x;
    for (int t = tid; t < 128 * 13; t += 256) sw[t] = W[t];
    if (tid < 13) sb[tid] = b[tid];
    __syncthreads();

    int warp = tid >> 5, lane = tid & 31;
    int i = blockIdx.x * 8 + warp;

    float h[4];
    #pragma unroll
    for (int q = 0; q < 4; q++) h[q] = H[i * 128 + q * 32 + lane];

    float z[13];
    #pragma unroll
    for (int f = 0; f < 13; f++) {
        float acc = 0.f;
        #pragma unroll
        for (int q = 0; q < 4; q++)
            acc = fmaf(h[q], sw[(q * 32 + lane) * 13 + f], acc);
        #pragma unroll
        for (int off = 16; off; off >>= 1)
            acc += __shfl_xor_sync(~0u, acc, off);
        z[f] = acc + sb[f];
    }
    float m = z[0];
    #pragma unroll
    for (int f = 1; f < 13; f++) m = fmaxf(m, z[f]);
    float s = 0.f;
    #pragma unroll
    for (int f = 0; f < 13; f++) s += expf(z[f] - m);
    float lse = m + logf(s);
    if (lane == 0) {
        #pragma unroll
        for (int f = 0; f < 13; f++) out[i * 13 + f] = z[f] - lse;
    }
}

// ---------------- launch ----------------
extern "C" void kernel_launch(void* const* d_in, const int* in_sizes, int n_in,
                              void* d_out, int out_size)
{
    const float* x   = (const float*)d_in[0];
    const float* w1  = (const float*)d_in[1];
    const float* b1  = (const float*)d_in[2];
    const float* w2  = (const float*)d_in[3];
    const float* b2  = (const float*)d_in[4];
    const float* w3  = (const float*)d_in[5];
    const float* b3  = (const float*)d_in[6];
    const float* wl1 = (const float*)d_in[7];
    const float* bl1 = (const float*)d_in[8];
    const float* wm1 = (const float*)d_in[9];
    const float* bm1 = (const float*)d_in[10];
    const float* wm2 = (const float*)d_in[11];
    const float* bm2 = (const float*)d_in[12];
    const float* wm3 = (const float*)d_in[13];
    const float* bm3 = (const float*)d_in[14];
    float* out = (float*)d_out;
    const int N = NPTS;

    float *feat, *u, *v, *sq, *h1, *h2, *h3; int* idx;
    cudaGetSymbolAddress((void**)&feat, g_feat);
    cudaGetSymbolAddress((void**)&u,    g_u);
    cudaGetSymbolAddress((void**)&v,    g_v);
    cudaGetSymbolAddress((void**)&sq,   g_sq);
    cudaGetSymbolAddress((void**)&idx,  g_idx);
    cudaGetSymbolAddress((void**)&h1,   g_h1);
    cudaGetSymbolAddress((void**)&h2,   g_h2);
    cudaGetSymbolAddress((void**)&h3,   g_h3);

    const size_t sh3   = 256 * 16 + 8 * 32 * 21 * 8;   // 47104 B
    const size_t shK64 = (size_t)33 * 64 * 8 + (size_t)33 * 128 * 8
                       + (size_t)64 * SDK * 4
                       + 256 * 20 * 4 + 256 * 20 * 2 + 32 + 64 * 4;  // ~115.5 KB
    cudaFuncSetAttribute((const void*)knn64_kernel,
                         cudaFuncAttributeMaxDynamicSharedMemorySize, (int)shK64);

    dim3 b64x4(64, 4);

    // ---- layer 1 (C=3) ----  (knn3 = 4th launch -> ncu capture slot)
    sqn_kernel<<<(N / 2) / 256, 256>>>(x, 3, 3, sq, N / 2);                 // 1
    sqn_kernel<<<(N / 2) / 256, 256>>>(x + (N / 2) * 3, 3, 3,
                                       sq + N / 2, N / 2);                  // 2
    uv_kernel<3><<<N / 4, b64x4>>>(x, 3, w1, u, v, N);                      // 3
    knn3_kernel<256, 8><<<N / 8, 256, sh3>>>(x, sq, idx, N);                // 4
    edge_max_kernel<<<N / 4, b64x4>>>(u, v, b1, idx, feat, 192, 0, N);      // 5

    // ---- layer 2 (C=64 on feat[:,0:64]) ----
    sqn_kernel<<<N / 256, 256>>>(feat, 192, 64, sq, N);
    knn64_kernel<<<N / 64, 256, shK64>>>(feat, 192, sq, idx, N);
    uv_kernel<64><<<N / 4, b64x4>>>(feat, 192, w2, u, v, N);
    edge_max_kernel<<<N / 4, b64x4>>>(u, v, b2, idx, feat, 192, 64, N);

    // ---- layer 3 (C=64 on feat[:,64:128]) ----
    sqn_kernel<<<N / 256, 256>>>(feat + 64, 192, 64, sq, N);
    knn64_kernel<<<N / 64, 256, shK64>>>(feat + 64, 192, sq, idx, N);
    uv_kernel<64><<<N / 4, b64x4>>>(feat + 64, 192, w3, u, v, N);
    edge_max_kernel<<<N / 4, b64x4>>>(u, v, b3, idx, feat, 192, 128, N);

    // ---- MLP head ----
    gemm_f2_64x256<<<dim3(4, 128), 256>>>(feat, 192, wl1, 1024, bl1, h1, 1024, 192);
    gemm_f2_64x256<<<dim3(1, 128), 256>>>(h1, 1024, wm1, 256, bm1, h2, 256, 1024);
    sgemm_bias_relu<<<dim3(2, 128), 256>>>(h2, 256, wm2, 128, bm2, h3, 128, 256, 1);
    final_logsoftmax<<<N / 8, 256>>>(h3, wm3, bm3, out, N);
}

// round 16
// speedup vs baseline: 1.0601x; 1.0601x over previous
#include <cuda_runtime.h>
#include <math.h>

#define KNN 20
#define NPTS 8192
typedef unsigned long long ull;
typedef unsigned short ushort_t;

// ---------------- scratch ----------------
__device__ __align__(256) float g_feat[NPTS * 192];
__device__ __align__(256) float g_u[NPTS * 64];
__device__ __align__(256) float g_v[NPTS * 64];
__device__ __align__(256) float g_sq[NPTS];
__device__ __align__(256) int   g_idx[NPTS * KNN];
__device__ __align__(256) float g_h1[NPTS * 1024];
__device__ __align__(256) float g_h2[NPTS * 256];
__device__ __align__(256) float g_h3[NPTS * 128];

__device__ __forceinline__ void fma2(ull& d, ull a, ull b) {
    asm("fma.rn.f32x2 %0, %1, %2, %0;" : "+l"(d) : "l"(a), "l"(b));
}
__device__ __forceinline__ float sum2(ull u) {
    return __uint_as_float((unsigned)u) + __uint_as_float((unsigned)(u >> 32));
}

// ---------------- squared norms (layer 1 only) ----------------
__global__ void sqn_kernel(const float* __restrict__ X, int ldx, int C,
                           float* __restrict__ sq, int N)
{
    int i = blockIdx.x * blockDim.x + threadIdx.x;
    if (i < N) {
        float s = 0.f;
        for (int c = 0; c < C; c++) { float v = X[i * ldx + c]; s = fmaf(v, v, s); }
        sq[i] = s;
    }
}

// ---------------- kNN C=3: pre-gated append-buffer selection (R14, committed) ----------------
template<int TJ, int WARPS>
__global__ void __launch_bounds__(256)
knn3_kernel(const float* __restrict__ X,
            const float* __restrict__ sqn,
            int* __restrict__ idx, int N)
{
    extern __shared__ float4 sh4[];
    float4* sP = sh4;                          // [TJ]
    float*  cd = (float*)(sP + TJ);            // WARPS*32*21
    int*    ci = (int*)(cd + WARPS * 32 * 21);

    const int warpId = threadIdx.x >> 5;
    const int lane   = threadIdx.x & 31;
    const int row    = blockIdx.x * WARPS + warpId;

    const float xa = -2.f * X[row * 3 + 0];
    const float xb = -2.f * X[row * 3 + 1];
    const float xc = -2.f * X[row * 3 + 2];

    float* myd = cd + (warpId * 32 + lane) * 21;
    int*   myi = ci + (warpId * 32 + lane) * 21;
    #pragma unroll
    for (int t = 0; t < KNN; t++) { myd[t] = INFINITY; myi[t] = 0x7fffffff; }
    int   count = 0;
    float worst = INFINITY;
    int   worstpos = 0;
    float lane_min = INFINITY;
    float wgate;

    {
        const float* xr = X + threadIdx.x * 3;
        sP[threadIdx.x] = make_float4(xr[0], xr[1], xr[2], sqn[threadIdx.x]);
    }
    __syncthreads();
    {
        float mn = INFINITY;
        #pragma unroll
        for (int q = 0; q < TJ / 32; q++) {
            float4 p = sP[q * 32 + lane];
            mn = fminf(mn, fmaf(xa, p.x, fmaf(xb, p.y, fmaf(xc, p.z, p.w))));
        }
        lane_min = mn;
        float m = mn;
        #pragma unroll
        for (int off = 16; off; off >>= 1)
            m = fmaxf(m, __shfl_xor_sync(~0u, m, off));
        wgate = m;
    }

    for (int base = 0; base < N; base += TJ) {
        __syncthreads();
        {
            const float* xr = X + (base + threadIdx.x) * 3;
            sP[threadIdx.x] = make_float4(xr[0], xr[1], xr[2], sqn[base + threadIdx.x]);
        }
        __syncthreads();

        float dv[TJ / 32];
        float mn = INFINITY;
        #pragma unroll
        for (int q = 0; q < TJ / 32; q++) {
            float4 p = sP[q * 32 + lane];
            float d = fmaf(xa, p.x, fmaf(xb, p.y, fmaf(xc, p.z, p.w)));
            dv[q] = d;
            mn = fminf(mn, d);
        }
        lane_min = fminf(lane_min, mn);
        if (mn < fminf(worst, wgate)) {
            #pragma unroll
            for (int q = 0; q < TJ / 32; q++) {
                float d = dv[q];
                int   j = base + q * 32 + lane;
                if (d < fminf(worst, wgate) && j != row) {
                    if (count < KNN) {
                        myd[count] = d;
                        myi[count] = j;
                        count++;
                        if (count == KNN) {
                            worst = -INFINITY;
                            #pragma unroll
                            for (int t = 0; t < KNN; t++) {
                                float v = myd[t];
                                if (v > worst) { worst = v; worstpos = t; }
                            }
                        }
                    } else {
                        myd[worstpos] = d;
                        myi[worstpos] = j;
                        worst = -INFINITY;
                        #pragma unroll
                        for (int t = 0; t < KNN; t++) {
                            float v = myd[t];
                            if (v > worst) { worst = v; worstpos = t; }
                        }
                    }
                }
            }
        }
        {
            float m = lane_min;
            #pragma unroll
            for (int off = 16; off; off >>= 1)
                m = fmaxf(m, __shfl_xor_sync(~0u, m, off));
            wgate = m;
        }
    }

    __syncwarp();
    for (int r = 0; r < KNN; r++) {
        float bv = INFINITY; int bj = 0x7fffffff, bp = 0, bl = lane;
        #pragma unroll
        for (int t = 0; t < KNN; t++) {
            float v = myd[t]; int jv = myi[t];
            if (v < bv || (v == bv && jv < bj)) { bv = v; bj = jv; bp = t; }
        }
        #pragma unroll
        for (int off = 16; off; off >>= 1) {
            float ov = __shfl_xor_sync(~0u, bv, off);
            int   oj = __shfl_xor_sync(~0u, bj, off);
            int   ol = __shfl_xor_sync(~0u, bl, off);
            int   op = __shfl_xor_sync(~0u, bp, off);
            if (ov < bv || (ov == bv && oj < bj)) { bv = ov; bj = oj; bl = ol; bp = op; }
        }
        if (lane == bl) myd[bp] = INFINITY;
        if (lane == 0)  idx[row * KNN + r] = bj;
        __syncwarp();
    }
}

// ---------------- kNN C=64 (R14 version: 256-cand tiles, 16x4 f32x2) ----------------
#define SDK 258
__global__ void __launch_bounds__(256, 1)
knn64_kernel(const float* __restrict__ X, int ldx, const float* __restrict__ sqn,
             int* __restrict__ idx, int N)
{
    extern __shared__ float sh[];
    float2*   Qs2   = (float2*)sh;                   // [33][64]
    float2*   Cs2   = Qs2 + 33 * 64;                 // [33][256] swizzled
    float*    sDist = (float*)(Cs2 + 33 * 256);      // [64][258]
    float*    Ld    = sDist + 64 * SDK;              // [256][21]
    ushort_t* Lj    = (ushort_t*)(Ld + 256 * 21);    // [256][21]
    float*    sThr  = (float*)(Lj + 256 * 21 + 8);   // [64]

    const int tid  = threadIdx.x;
    const int w    = tid >> 5, tx = tid & 31;
    const int rowg = w >> 1, colh = w & 1;
    const int rowBase = blockIdx.x * 64;

    if (tid < 64) sThr[tid] = INFINITY;

    {
        int r = tid >> 2, part = tid & 3;
        const float* xr = X + (rowBase + r) * ldx + part * 16;
        #pragma unroll
        for (int i = 0; i < 4; i++) {
            float4 v = *(const float4*)(xr + i * 4);
            int kp = part * 8 + i * 2;
            Qs2[kp * 64 + r]       = make_float2(v.x, v.y);
            Qs2[(kp + 1) * 64 + r] = make_float2(v.z, v.w);
        }
        if (part == 0) Qs2[32 * 64 + r] = make_float2(-0.5f, -0.5f);
    }

    const int selR = tid >> 2, selS = tid & 3;
    const int grow = rowBase + selR;
    float*    myLd = Ld + tid * 21;
    ushort_t* myLj = Lj + tid * 21;
    #pragma unroll
    for (int t = 0; t < KNN; t++) myLd[t] = INFINITY;
    float wd = INFINITY;
    int   wpos = 0;

    for (int base = 0; base < N; base += 256) {
        __syncthreads();
        {
            int q = tid & 15, c0 = tid >> 4;
            int sxr = (q & 7) * 2;
            #pragma unroll
            for (int i = 0; i < 16; i++) {
                int c = c0 + i * 16;
                float4 v = *(const float4*)(X + (base + c) * ldx + q * 4);
                int cs = c ^ sxr;
                Cs2[(2 * q)     * 256 + cs] = make_float2(v.x, v.y);
                Cs2[(2 * q + 1) * 256 + cs] = make_float2(v.z, v.w);
            }
            Cs2[32 * 256 + tid] = make_float2(sqn[base + tid], 0.f);
        }
        __syncthreads();

        ull acc[16][4];
        #pragma unroll
        for (int m = 0; m < 16; m++)
            #pragma unroll
            for (int n = 0; n < 4; n++) acc[m][n] = 0ull;

        #pragma unroll 3
        for (int kp = 0; kp < 33; kp++) {
            int sxr = ((kp >> 1) & 7) * 2;
            const float2* bb = Cs2 + kp * 256;
            ulonglong2 B0 = *(const ulonglong2*)(bb + ((colh * 128 + tx * 2) ^ sxr));
            ulonglong2 B1 = *(const ulonglong2*)(bb + ((colh * 128 + 64 + tx * 2) ^ sxr));
            const ulonglong2* pa = (const ulonglong2*)(Qs2 + kp * 64 + rowg * 16);
            #pragma unroll
            for (int i = 0; i < 8; i++) {
                ulonglong2 A = pa[i];
                fma2(acc[2*i][0],   A.x, B0.x); fma2(acc[2*i][1],   A.x, B0.y);
                fma2(acc[2*i][2],   A.x, B1.x); fma2(acc[2*i][3],   A.x, B1.y);
                fma2(acc[2*i+1][0], A.y, B0.x); fma2(acc[2*i+1][1], A.y, B0.y);
                fma2(acc[2*i+1][2], A.y, B1.x); fma2(acc[2*i+1][3], A.y, B1.y);
            }
        }

        #pragma unroll
        for (int i = 0; i < 16; i++) {
            int row = rowg * 16 + i;
            float* dr = sDist + row * SDK + colh * 128 + tx * 2;
            *(float2*)(dr)      = make_float2(-2.f * sum2(acc[i][0]), -2.f * sum2(acc[i][1]));
            *(float2*)(dr + 64) = make_float2(-2.f * sum2(acc[i][2]), -2.f * sum2(acc[i][3]));
        }
        __syncthreads();

        {
            const float* sp = sDist + selR * SDK + selS * 64;
            const float thrS = sThr[selR];
            float gate = fminf(wd, thrS);
            #pragma unroll
            for (int blk = 0; blk < 2; blk++) {
                const float* bp = sp + blk * 32;
                float mn = INFINITY;
                #pragma unroll
                for (int o = 0; o < 32; o += 2) {
                    float2 v = *(const float2*)(bp + o);
                    mn = fminf(mn, fminf(v.x, v.y));
                }
                if (mn < gate) {
                    int jb = base + selS * 64 + blk * 32;
                    #pragma unroll 8
                    for (int o = 0; o < 32; o++) {
                        float d = bp[o];
                        if (d < gate && (jb + o) != grow) {
                            myLd[wpos] = d;
                            myLj[wpos] = (ushort_t)(jb + o);
                            wd = -INFINITY;
                            #pragma unroll
                            for (int t = 0; t < KNN; t++) {
                                float v = myLd[t];
                                if (v > wd) { wd = v; wpos = t; }
                            }
                            gate = fminf(wd, thrS);
                        }
                    }
                }
            }
            if (wd < sThr[selR]) sThr[selR] = wd;   // racy min: valid upper bound
        }
    }

    __syncthreads();
    if (selS == 0) {
        #pragma unroll 1
        for (int k = 0; k < KNN; k++) {
            float bd = INFINITY; int bj = 0x7fffffff;
            int bslot = 0;
            #pragma unroll 1
            for (int tt = 0; tt < 4; tt++) {
                int lb = (tid + tt) * 21;
                #pragma unroll 4
                for (int t = 0; t < KNN; t++) {
                    float d = Ld[lb + t];
                    int   j = (int)Lj[lb + t];
                    if (d < bd || (d == bd && j < bj)) { bd = d; bj = j; bslot = lb + t; }
                }
            }
            Ld[bslot] = INFINITY;
            idx[grow * KNN + k] = bj;
        }
    }
}

// ---------------- EdgeConv U/V ----------------
template<int C>
__global__ void uv_kernel(const float* __restrict__ X, int ldx,
                          const float* __restrict__ w,
                          float* __restrict__ U, float* __restrict__ V, int N)
{
    __shared__ float sw[2 * C * 64];
    __shared__ float sx[4][C > 0 ? C : 1];
    int tid = threadIdx.y * 64 + threadIdx.x;
    for (int t = tid; t < 2 * C * 64; t += 256) sw[t] = w[t];
    int i = blockIdx.x * 4 + threadIdx.y;
    for (int c = threadIdx.x; c < C; c += 64) sx[threadIdx.y][c] = X[i * ldx + c];
    __syncthreads();

    int f = threadIdx.x;
    float u = 0.f, v = 0.f;
    #pragma unroll
    for (int c = 0; c < C; c++) {
        float xc = sx[threadIdx.y][c];
        u = fmaf(xc, sw[c * 64 + f], u);
        v = fmaf(xc, sw[(C + c) * 64 + f], v);
    }
    U[i * 64 + f] = u - v;
    V[i * 64 + f] = v;
}

// ---------------- neighbor gather-max + relu, with fused row-norm output ----------------
__global__ void edge_max_kernel(const float* __restrict__ U, const float* __restrict__ V,
                                const float* __restrict__ b, const int* __restrict__ idx,
                                float* __restrict__ out, int ldo, int colofs,
                                float* __restrict__ sqout, int N)
{
    __shared__ int   sidx[4][KNN];
    __shared__ float spart[4][2];
    int i = blockIdx.x * 4 + threadIdx.y;
    if (threadIdx.x < KNN) sidx[threadIdx.y][threadIdx.x] = idx[i * KNN + threadIdx.x];
    __syncthreads();

    int f = threadIdx.x;
    float m = -INFINITY;
    #pragma unroll
    for (int t = 0; t < KNN; t++) {
        int j = sidx[threadIdx.y][t];
        m = fmaxf(m, V[j * 64 + f]);
    }
    float val = fmaxf(U[i * 64 + f] + b[f] + m, 0.f);
    out[i * ldo + colofs + f] = val;

    if (sqout != nullptr) {   // uniform across block
        float s = val * val;
        #pragma unroll
        for (int off = 16; off; off >>= 1)
            s += __shfl_xor_sync(~0u, s, off);
        if ((f & 31) == 0) spart[threadIdx.y][f >> 5] = s;
        __syncthreads();
        if (f == 0) sqout[i] = spart[threadIdx.y][0] + spart[threadIdx.y][1];
    }
}

// ---------------- f32x2 SGEMM 64x256, fused bias+relu ----------------
__global__ void __launch_bounds__(256, 1)
gemm_f2_64x256(const float* __restrict__ A, int lda,
               const float* __restrict__ B, int ldb,
               const float* __restrict__ bias,
               float* __restrict__ C, int ldc, int K)
{
    __shared__ float2 As2[16][64];
    __shared__ float2 Bs2[16][256];

    const int tid = threadIdx.x;
    const int ty  = tid >> 5, tx = tid & 31;
    const int rowBase = blockIdx.y * 64;
    const int colBase = blockIdx.x * 256;

    ull acc[8][8];
    #pragma unroll
    for (int m = 0; m < 8; m++)
        #pragma unroll
        for (int n = 0; n < 8; n++) acc[m][n] = 0ull;

    const int ar = tid >> 2, ac = (tid & 3) * 8;
    const int bkp = tid >> 4, bc0 = (tid & 15) * 4;

    for (int k0 = 0; k0 < K; k0 += 32) {
        float4 v0 = *(const float4*)&A[(rowBase + ar) * lda + k0 + ac];
        float4 v1 = *(const float4*)&A[(rowBase + ar) * lda + k0 + ac + 4];
        float4 blo[4], bhi[4];
        #pragma unroll
        for (int rep = 0; rep < 4; rep++) {
            int col = colBase + rep * 64 + bc0;
            blo[rep] = *(const float4*)&B[(k0 + 2 * bkp) * ldb + col];
            bhi[rep] = *(const float4*)&B[(k0 + 2 * bkp + 1) * ldb + col];
        }
        __syncthreads();
        As2[(ac >> 1) + 0][ar] = make_float2(v0.x, v0.y);
        As2[(ac >> 1) + 1][ar] = make_float2(v0.z, v0.w);
        As2[(ac >> 1) + 2][ar] = make_float2(v1.x, v1.y);
        As2[(ac >> 1) + 3][ar] = make_float2(v1.z, v1.w);
        #pragma unroll
        for (int rep = 0; rep < 4; rep++) {
            int c = rep * 64 + bc0;
            Bs2[bkp][c + 0] = make_float2(blo[rep].x, bhi[rep].x);
            Bs2[bkp][c + 1] = make_float2(blo[rep].y, bhi[rep].y);
            Bs2[bkp][c + 2] = make_float2(blo[rep].z, bhi[rep].z);
            Bs2[bkp][c + 3] = make_float2(blo[rep].w, bhi[rep].w);
        }
        __syncthreads();

        #pragma unroll 4
        for (int kp = 0; kp < 16; kp++) {
            ull a[8], b[8];
            const ulonglong2* pa0 = (const ulonglong2*)(&As2[kp][ty * 4]);
            const ulonglong2* pa1 = (const ulonglong2*)(&As2[kp][32 + ty * 4]);
            ulonglong2 A0 = pa0[0], A1 = pa0[1], A2 = pa1[0], A3 = pa1[1];
            a[0] = A0.x; a[1] = A0.y; a[2] = A1.x; a[3] = A1.y;
            a[4] = A2.x; a[5] = A2.y; a[6] = A3.x; a[7] = A3.y;
            #pragma unroll
            for (int ch = 0; ch < 4; ch++) {
                ulonglong2 Bv = *(const ulonglong2*)(&Bs2[kp][ch * 64 + tx * 2]);
                b[2 * ch] = Bv.x; b[2 * ch + 1] = Bv.y;
            }
            #pragma unroll
            for (int m = 0; m < 8; m++)
                #pragma unroll
                for (int n = 0; n < 8; n++)
                    fma2(acc[m][n], a[m], b[n]);
        }
    }

    #pragma unroll
    for (int m = 0; m < 8; m++) {
        int row = rowBase + ((m < 4) ? (ty * 4 + m) : (32 + ty * 4 + (m - 4)));
        #pragma unroll
        for (int ch = 0; ch < 4; ch++) {
            int col = colBase + ch * 64 + tx * 2;
            float d0 = fmaxf(sum2(acc[m][2 * ch])     + bias[col],     0.f);
            float d1 = fmaxf(sum2(acc[m][2 * ch + 1]) + bias[col + 1], 0.f);
            *(float2*)&C[row * ldc + col] = make_float2(d0, d1);
        }
    }
}

// ---------------- small SGEMM (wm2) ----------------
__global__ void sgemm_bias_relu(const float* __restrict__ A, int lda,
                                const float* __restrict__ B, int ldb,
                                const float* __restrict__ bias,
                                float* __restrict__ Cm, int ldc,
                                int Kdim, int relu)
{
    __shared__ float As[16][68];
    __shared__ float Bs[16][64];
    const int tid = threadIdx.x;
    const int tx = tid & 15, ty = tid >> 4;
    const int rowBase = blockIdx.y * 64;
    const int colBase = blockIdx.x * 64;

    const int ar = tid >> 2, akq = (tid & 3) * 4;
    const int bk = tid >> 4, bc = (tid & 15) * 4;

    float acc[4][4] = {};
    for (int k0 = 0; k0 < Kdim; k0 += 16) {
        float4 av = *(const float4*)&A[(rowBase + ar) * lda + k0 + akq];
        float4 bv = *(const float4*)&B[(k0 + bk) * ldb + colBase + bc];
        __syncthreads();
        As[akq + 0][ar] = av.x; As[akq + 1][ar] = av.y;
        As[akq + 2][ar] = av.z; As[akq + 3][ar] = av.w;
        *(float4*)&Bs[bk][bc] = bv;
        __syncthreads();
        #pragma unroll
        for (int kk = 0; kk < 16; kk++) {
            float a[4], bb[4];
            #pragma unroll
            for (int m = 0; m < 4; m++) a[m] = As[kk][ty * 4 + m];
            #pragma unroll
            for (int n = 0; n < 4; n++) bb[n] = Bs[kk][tx * 4 + n];
            #pragma unroll
            for (int m = 0; m < 4; m++)
                #pragma unroll
                for (int n = 0; n < 4; n++)
                    acc[m][n] = fmaf(a[m], bb[n], acc[m][n]);
        }
    }
    #pragma unroll
    for (int m = 0; m < 4; m++) {
        int r = rowBase + ty * 4 + m;
        #pragma unroll
        for (int n = 0; n < 4; n++) {
            int c = colBase + tx * 4 + n;
            float v = acc[m][n] + bias[c];
            if (relu) v = fmaxf(v, 0.f);
            Cm[r * ldc + c] = v;
        }
    }
}

// ---------------- final 128->13 + log_softmax ----------------
__global__ void final_logsoftmax(const float* __restrict__ H,
                                 const float* __restrict__ W,
                                 const float* __restrict__ b,
                                 float* __restrict__ out, int N)
{
    __shared__ float sw[128 * 13];
    __shared__ float sb[13];
    int tid = threadIdx.x;
    for (int t = tid; t < 128 * 13; t += 256) sw[t] = W[t];
    if (tid < 13) sb[tid] = b[tid];
    __syncthreads();

    int warp = tid >> 5, lane = tid & 31;
    int i = blockIdx.x * 8 + warp;

    float h[4];
    #pragma unroll
    for (int q = 0; q < 4; q++) h[q] = H[i * 128 + q * 32 + lane];

    float z[13];
    #pragma unroll
    for (int f = 0; f < 13; f++) {
        float acc = 0.f;
        #pragma unroll
        for (int q = 0; q < 4; q++)
            acc = fmaf(h[q], sw[(q * 32 + lane) * 13 + f], acc);
        #pragma unroll
        for (int off = 16; off; off >>= 1)
            acc += __shfl_xor_sync(~0u, acc, off);
        z[f] = acc + sb[f];
    }
    float m = z[0];
    #pragma unroll
    for (int f = 1; f < 13; f++) m = fmaxf(m, z[f]);
    float s = 0.f;
    #pragma unroll
    for (int f = 0; f < 13; f++) s += expf(z[f] - m);
    float lse = m + logf(s);
    if (lane == 0) {
        #pragma unroll
        for (int f = 0; f < 13; f++) out[i * 13 + f] = z[f] - lse;
    }
}

// ---------------- launch ----------------
extern "C" void kernel_launch(void* const* d_in, const int* in_sizes, int n_in,
                              void* d_out, int out_size)
{
    const float* x   = (const float*)d_in[0];
    const float* w1  = (const float*)d_in[1];
    const float* b1  = (const float*)d_in[2];
    const float* w2  = (const float*)d_in[3];
    const float* b2  = (const float*)d_in[4];
    const float* w3  = (const float*)d_in[5];
    const float* b3  = (const float*)d_in[6];
    const float* wl1 = (const float*)d_in[7];
    const float* bl1 = (const float*)d_in[8];
    const float* wm1 = (const float*)d_in[9];
    const float* bm1 = (const float*)d_in[10];
    const float* wm2 = (const float*)d_in[11];
    const float* bm2 = (const float*)d_in[12];
    const float* wm3 = (const float*)d_in[13];
    const float* bm3 = (const float*)d_in[14];
    float* out = (float*)d_out;
    const int N = NPTS;

    float *feat, *u, *v, *sq, *h1, *h2, *h3; int* idx;
    cudaGetSymbolAddress((void**)&feat, g_feat);
    cudaGetSymbolAddress((void**)&u,    g_u);
    cudaGetSymbolAddress((void**)&v,    g_v);
    cudaGetSymbolAddress((void**)&sq,   g_sq);
    cudaGetSymbolAddress((void**)&idx,  g_idx);
    cudaGetSymbolAddress((void**)&h1,   g_h1);
    cudaGetSymbolAddress((void**)&h2,   g_h2);
    cudaGetSymbolAddress((void**)&h3,   g_h3);

    const size_t sh3   = 256 * 16 + 8 * 32 * 21 * 8;   // 47104 B
    const size_t shK64 = (size_t)(33 * 64 + 33 * 256) * 8
                       + (size_t)64 * SDK * 4
                       + 256 * 21 * 4 + 256 * 21 * 2 + 16 + 64 * 4;  // ~213 KB
    cudaFuncSetAttribute((const void*)knn64_kernel,
                         cudaFuncAttributeMaxDynamicSharedMemorySize, (int)shK64);

    dim3 b64x4(64, 4);

    // ---- layer 1 (C=3) ----  (knn3 = 4th launch -> ncu capture slot)
    sqn_kernel<<<(N / 2) / 256, 256>>>(x, 3, 3, sq, N / 2);                 // 1
    sqn_kernel<<<(N / 2) / 256, 256>>>(x + (N / 2) * 3, 3, 3,
                                       sq + N / 2, N / 2);                  // 2
    uv_kernel<3><<<N / 4, b64x4>>>(x, 3, w1, u, v, N);                      // 3
    knn3_kernel<256, 8><<<N / 8, 256, sh3>>>(x, sq, idx, N);                // 4
    edge_max_kernel<<<N / 4, b64x4>>>(u, v, b1, idx, feat, 192, 0, sq, N);  // 5 (+norms)

    // ---- layer 2 (C=64 on feat[:,0:64]) ----
    knn64_kernel<<<N / 64, 256, shK64>>>(feat, 192, sq, idx, N);
    uv_kernel<64><<<N / 4, b64x4>>>(feat, 192, w2, u, v, N);
    edge_max_kernel<<<N / 4, b64x4>>>(u, v, b2, idx, feat, 192, 64, sq, N); // (+norms)

    // ---- layer 3 (C=64 on feat[:,64:128]) ----
    knn64_kernel<<<N / 64, 256, shK64>>>(feat + 64, 192, sq, idx, N);
    uv_kernel<64><<<N / 4, b64x4>>>(feat + 64, 192, w3, u, v, N);
    edge_max_kernel<<<N / 4, b64x4>>>(u, v, b3, idx, feat, 192, 128, nullptr, N);

    // ---- MLP head ----
    gemm_f2_64x256<<<dim3(4, 128), 256>>>(feat, 192, wl1, 1024, bl1, h1, 1024, 192);
    gemm_f2_64x256<<<dim3(1, 128), 256>>>(h1, 1024, wm1, 256, bm1, h2, 256, 1024);
    sgemm_bias_relu<<<dim3(2, 128), 256>>>(h2, 256, wm2, 128, bm2, h3, 128, 256, 1);
    final_logsoftmax<<<N / 8, 256>>>(h3, wm3, bm3, out, N);
}